// round 12
// baseline (speedup 1.0000x reference)
#include <cuda_runtime.h>
#include <cstdint>

#define CIN  10
#define C    64
#define SMAX 30001
#define EPS  1e-3f
#define FULLMASK 0xffffffffu

typedef unsigned long long u64;

// ---------------- parameter staging (read by k_pipe into shared) ----------------
struct Params {
    u64   Wfp[32 * CIN];   // BN-folded linear weights, channel-pair packed
    u64   biasp[32];
    u64   dwp[32];
    float xg[C];
};
__device__ Params g_stage;

// ---------------- device scratch ----------------
__device__ float g_m1[CIN];
__device__ float g_m2[55];
__device__ float g_Wf[C * CIN];
__device__ float g_bias[C];
__device__ float g_gsum[C];
__device__ int   g_segstart[SMAX];
// per-pillar partials, 2 slots (pillar-start subtile / spill subtile)
__device__ float g_pmax[(size_t)2 * SMAX * C];
__device__ float g_psum[(size_t)2 * SMAX * C];

// ---------------- packed f32x2 / bf16 helpers ----------------
__device__ __forceinline__ u64 pack2(float lo, float hi) {
    u64 r; asm("mov.b64 %0, {%1, %2};" : "=l"(r) : "f"(lo), "f"(hi)); return r;
}
__device__ __forceinline__ void unpack2(u64 v, float& lo, float& hi) {
    asm("mov.b64 {%0, %1}, %2;" : "=f"(lo), "=f"(hi) : "l"(v));
}
__device__ __forceinline__ u64 fma2(u64 a, u64 b, u64 c) {
    u64 d; asm("fma.rn.f32x2 %0, %1, %2, %3;" : "=l"(d) : "l"(a), "l"(b), "l"(c)); return d;
}
__device__ __forceinline__ u64 mul2(u64 a, u64 b) {
    u64 d; asm("mul.rn.f32x2 %0, %1, %2;" : "=l"(d) : "l"(a), "l"(b)); return d;
}
// pack two f32 -> bf16x2 (hi goes to upper half)
__device__ __forceinline__ unsigned int cvt2bf(float hi, float lo) {
    unsigned int r;
    asm("cvt.rn.satfinite.bf16x2.f32 %0, %1, %2;" : "=r"(r) : "f"(hi), "f"(lo));
    return r;
}

__device__ __forceinline__ float sigmoidf_fast(float z) {
    return __fdividef(1.0f, 1.0f + __expf(-z));
}
__device__ __forceinline__ float warp_sum(float v) {
#pragma unroll
    for (int o = 16; o > 0; o >>= 1) v += __shfl_down_sync(FULLMASK, v, o);
    return v;
}

// ---------------- K1: zero accumulators + segment boundaries ----------------
__global__ void k_bounds(const int* __restrict__ unq, int n, int s_count) {
    if (blockIdx.x == 0) {
        int t = threadIdx.x;
        if (t < CIN) g_m1[t] = 0.0f;
        if (t < 55)  g_m2[t] = 0.0f;
        if (t < C)   g_gsum[t] = 0.0f;
    }
    int i = blockIdx.x * blockDim.x + threadIdx.x;
    if (i >= n) return;
    int cur = unq[i];
    if (i == 0) {
        for (int t = 0; t <= cur; t++) g_segstart[t] = 0;
    } else {
        int prev = unq[i - 1];
        for (int t = prev + 1; t <= cur; t++) g_segstart[t] = i;
    }
    if (i == n - 1) {
        for (int t = cur + 1; t <= s_count; t++) g_segstart[t] = n;
    }
}

// ---------------- K2: input first/second moments ----------------
__global__ void k_moments(const float* __restrict__ inp, int n) {
    float a1[CIN];
    float a2[55];
#pragma unroll
    for (int k = 0; k < CIN; k++) a1[k] = 0.0f;
#pragma unroll
    for (int k = 0; k < 55; k++) a2[k] = 0.0f;

    int stride = gridDim.x * blockDim.x;
    for (int i = blockIdx.x * blockDim.x + threadIdx.x; i < n; i += stride) {
        const float* row = inp + (size_t)i * CIN;
        float v[CIN];
#pragma unroll
        for (int k = 0; k < CIN; k++) v[k] = __ldg(row + k);
        int t = 0;
#pragma unroll
        for (int j = 0; j < CIN; j++) {
            a1[j] += v[j];
#pragma unroll
            for (int k = j; k < CIN; k++) { a2[t] += v[j] * v[k]; t++; }
        }
    }

    int lane = threadIdx.x & 31;
#pragma unroll
    for (int j = 0; j < CIN; j++) {
        float r = warp_sum(a1[j]);
        if (lane == 0) atomicAdd(&g_m1[j], r);
    }
#pragma unroll
    for (int t = 0; t < 55; t++) {
        float r = warp_sum(a2[t]);
        if (lane == 0) atomicAdd(&g_m2[t], r);
    }
}

// ---------------- K3: fold BN into linear + stage packed params ----------------
__global__ void k_fold(const float* __restrict__ W, const float* __restrict__ gamma,
                       const float* __restrict__ beta, const float* __restrict__ dw1,
                       int n) {
    int c = threadIdx.x;
    if (c < C) {
        float invn = 1.0f / (float)n;
        float wr[CIN];
#pragma unroll
        for (int k = 0; k < CIN; k++) wr[k] = W[c * CIN + k];

        float mu = 0.0f;
#pragma unroll
        for (int k = 0; k < CIN; k++) mu += wr[k] * g_m1[k];
        mu *= invn;

        float ex2 = 0.0f;
        int t = 0;
#pragma unroll
        for (int j = 0; j < CIN; j++) {
#pragma unroll
            for (int k = j; k < CIN; k++) {
                float f = wr[j] * wr[k] * g_m2[t];
                ex2 += (k == j) ? f : 2.0f * f;
                t++;
            }
        }
        ex2 *= invn;
        float var = ex2 - mu * mu;
        float alpha = gamma[c] * rsqrtf(var + EPS);
        g_bias[c] = beta[c] - mu * alpha;
#pragma unroll
        for (int k = 0; k < CIN; k++) g_Wf[c * CIN + k] = alpha * wr[k];
    }
    __syncthreads();
    if (c < 32) {
#pragma unroll
        for (int k = 0; k < CIN; k++)
            g_stage.Wfp[c * CIN + k] = pack2(g_Wf[(2 * c) * CIN + k],
                                             g_Wf[(2 * c + 1) * CIN + k]);
        g_stage.biasp[c] = pack2(g_bias[2 * c], g_bias[2 * c + 1]);
        g_stage.dwp[c]   = pack2(dw1[2 * c], dw1[2 * c + 1]);
    }
}

// ---------------- K4: g = sum over points of relu(x), channel-per-thread ----------------
#define GP_TILE 256
__global__ __launch_bounds__(256) void k_gpass(const float* __restrict__ inp, int n) {
    __shared__ __align__(16) float s_v[GP_TILE * 12];
    __shared__ float s_acc[C];

    int t = threadIdx.x;
    int c = t & 63, g = t >> 6;

    float w[CIN];
#pragma unroll
    for (int k = 0; k < CIN; k++) w[k] = g_Wf[c * CIN + k];
    float b = g_bias[c];
    if (t < C) s_acc[t] = 0.0f;

    float acc = 0.0f;
    for (int base = blockIdx.x * GP_TILE; base < n; base += gridDim.x * GP_TILE) {
        int cnt = n - base; if (cnt > GP_TILE) cnt = GP_TILE;
        __syncthreads();
        for (int i = t; i < cnt * CIN; i += 256) {
            int r = i / CIN, k = i - r * CIN;
            s_v[r * 12 + k] = inp[(size_t)base * CIN + i];
        }
        __syncthreads();
        int p0 = g * 64, p1 = p0 + 64; if (p1 > cnt) p1 = cnt;
        for (int p = p0; p < p1; p++) {
            const float* vr = s_v + p * 12;
            float4 va = *reinterpret_cast<const float4*>(vr);
            float4 vb = *reinterpret_cast<const float4*>(vr + 4);
            float2 vc = *reinterpret_cast<const float2*>(vr + 8);
            float x = b;
            x += w[0] * va.x; x += w[1] * va.y; x += w[2] * va.z; x += w[3] * va.w;
            x += w[4] * vb.x; x += w[5] * vb.y; x += w[6] * vb.z; x += w[7] * vb.w;
            x += w[8] * vc.x; x += w[9] * vc.y;
            acc += fmaxf(x, 0.0f);
        }
    }
    atomicAdd(&s_acc[c], acc);
    __syncthreads();
    if (t < C) atomicAdd(&g_gsum[t], s_acc[t]);
}

// ---------------- K5: global branch -> stage xg ----------------
__global__ void k_xg(const float* __restrict__ dw2, const float* __restrict__ pw2, int n) {
    __shared__ float t[C];
    int c = threadIdx.x;
    if (c < C) t[c] = fmaxf(dw2[c] * (g_gsum[c] / (float)n), 0.0f);
    __syncthreads();
    if (c >= C) return;
    float acc = 0.0f;
#pragma unroll
    for (int k = 0; k < C; k++) acc += pw2[c * C + k] * t[k];
    g_stage.xg[c] = acc;
}

// ---------------- K6: fused pipeline, bf16 mma.sync phase B ----------------
// dynamic shared layout (bytes):
//   xT   [64][130] f32      @ 0      (33280)  x then xi, transposed [ch][pt]
//   swA  [128 pt][144B]     @ 33280  (18432)  sw bf16, row = point, 64 k + pad
//   pwB  [64 n][144B]       @ 51712  (9216)   pw1 bf16, row = out-ch, 64 k + pad
//   Wfp  [32*10]   u64      @ 60928  (2560)
//   bp   [32]      u64      @ 63488  (256)
//   dwp  [32]      u64      @ 63744  (256)
//   xg   [64]      f32      @ 64000  (256)
//   s_u  [128]     int      @ 64256  (512)
#define XT_S    130
#define SWA_STRIDE_B 144
#define PWB_STRIDE_B 144
#define OFF_SWA 33280
#define OFF_PWB 51712
#define OFF_WFP 60928
#define OFF_BP  63488
#define OFF_DWP 63744
#define OFF_XG  64000
#define OFF_U   64256
#define PIPE_SMEM 64768

__global__ __launch_bounds__(128, 3) void k_pipe(const float* __restrict__ inp,
                                                 const float* __restrict__ pw1,
                                                 const int* __restrict__ unq,
                                                 int n) {
    extern __shared__ __align__(16) char dsm[];
    float* xT   = reinterpret_cast<float*>(dsm);
    unsigned int* swA32 = reinterpret_cast<unsigned int*>(dsm + OFF_SWA);
    unsigned int* pwB32 = reinterpret_cast<unsigned int*>(dsm + OFF_PWB);
    const ulonglong2* Wfp2 = reinterpret_cast<const ulonglong2*>(dsm + OFF_WFP);
    u64*   wfpw = reinterpret_cast<u64*>(dsm + OFF_WFP);
    u64*   bp   = reinterpret_cast<u64*>(dsm + OFF_BP);
    u64*   dwp  = reinterpret_cast<u64*>(dsm + OFF_DWP);
    float* s_xg = reinterpret_cast<float*>(dsm + OFF_XG);
    int*   s_u  = reinterpret_cast<int*>(dsm + OFF_U);

    int li = threadIdx.x;
    int base = blockIdx.x * 128;
    int cnt = n - base; if (cnt > 128) cnt = 128;

    // staging: pw1 [c][k] f32 -> pwB bf16 rows (n-major, k contiguous)
    for (int idx = li; idx < 2048; idx += 128) {
        int c = idx >> 5, kp = idx & 31;
        float2 v = __ldg(reinterpret_cast<const float2*>(pw1 + c * C + 2 * kp));
        pwB32[c * 36 + kp] = cvt2bf(v.y, v.x);
    }
    for (int t = li; t < 32 * CIN; t += 128) wfpw[t] = g_stage.Wfp[t];
    if (li < 32) { bp[li] = g_stage.biasp[li]; dwp[li] = g_stage.dwp[li]; }
    if (li < C) s_xg[li] = g_stage.xg[li];
    if (li < cnt) s_u[li] = __ldg(unq + base + li);
    __syncthreads();

    // ---- phase A: per-point folded linear + relu + swish (x -> xT, sw -> swA bf16) ----
    if (li < cnt) {
        const float* row = inp + (size_t)(base + li) * CIN;
        u64 vd[CIN];
#pragma unroll
        for (int k = 0; k < CIN; k++) {
            float f = __ldg(row + k);
            vd[k] = pack2(f, f);
        }
#pragma unroll
        for (int cp = 0; cp < 32; cp++) {
            ulonglong2 wA = Wfp2[cp * 5 + 0];
            ulonglong2 wB = Wfp2[cp * 5 + 1];
            ulonglong2 wC = Wfp2[cp * 5 + 2];
            ulonglong2 wD = Wfp2[cp * 5 + 3];
            ulonglong2 wE = Wfp2[cp * 5 + 4];
            u64 a = bp[cp];
            a = fma2(wA.x, vd[0], a); a = fma2(wA.y, vd[1], a);
            a = fma2(wB.x, vd[2], a); a = fma2(wB.y, vd[3], a);
            a = fma2(wC.x, vd[4], a); a = fma2(wC.y, vd[5], a);
            a = fma2(wD.x, vd[6], a); a = fma2(wD.y, vd[7], a);
            a = fma2(wE.x, vd[8], a); a = fma2(wE.y, vd[9], a);
            float lo, hi; unpack2(a, lo, hi);
            lo = fmaxf(lo, 0.0f); hi = fmaxf(hi, 0.0f);
            xT[(2 * cp) * XT_S + li]     = lo;
            xT[(2 * cp + 1) * XT_S + li] = hi;
            u64 sp = mul2(pack2(lo, hi), dwp[cp]);
            float sa, sb; unpack2(sp, sa, sb);
            float swa = sa * sigmoidf_fast(sa);
            float swb = sb * sigmoidf_fast(sb);
            swA32[li * 36 + cp] = cvt2bf(swb, swa);   // lo16 = k even, hi16 = k odd
        }
    } else {
#pragma unroll
        for (int c = 0; c < C; c++) xT[c * XT_S + li] = 0.0f;
#pragma unroll
        for (int cp = 0; cp < 32; cp++) swA32[li * 36 + cp] = 0u;
    }
    __syncthreads();

    // ---- phase B: tensor-core GEMM xl[p][c] = sum_k sw[p][k] * pwB[c][k] ----
    {
        int w = li >> 5, lane = li & 31;
        int mbase = w * 32;

        unsigned swA_base = (unsigned)__cvta_generic_to_shared(dsm + OFF_SWA);
        unsigned pwB_base = (unsigned)__cvta_generic_to_shared(dsm + OFF_PWB);

        float acc[2][8][4];
#pragma unroll
        for (int mt = 0; mt < 2; mt++)
#pragma unroll
            for (int j = 0; j < 8; j++)
#pragma unroll
                for (int r = 0; r < 4; r++) acc[mt][j][r] = 0.0f;

#pragma unroll
        for (int t = 0; t < 4; t++) {
            unsigned int a[2][4];
#pragma unroll
            for (int mt = 0; mt < 2; mt++) {
                unsigned addrA = swA_base
                    + (mbase + mt * 16 + (lane & 15)) * SWA_STRIDE_B
                    + (lane >> 4) * 16 + t * 32;
                asm volatile(
                    "ldmatrix.sync.aligned.m8n8.x4.shared.b16 {%0,%1,%2,%3}, [%4];"
                    : "=r"(a[mt][0]), "=r"(a[mt][1]), "=r"(a[mt][2]), "=r"(a[mt][3])
                    : "r"(addrA));
            }
#pragma unroll
            for (int j = 0; j < 8; j++) {
                unsigned int b0, b1;
                unsigned addrB = pwB_base
                    + (8 * j + (lane & 7)) * PWB_STRIDE_B
                    + ((lane >> 3) & 1) * 16 + t * 32;
                asm volatile(
                    "ldmatrix.sync.aligned.m8n8.x2.shared.b16 {%0,%1}, [%2];"
                    : "=r"(b0), "=r"(b1) : "r"(addrB));
#pragma unroll
                for (int mt = 0; mt < 2; mt++) {
                    asm volatile(
                        "mma.sync.aligned.m16n8k16.row.col.f32.bf16.bf16.f32 "
                        "{%0,%1,%2,%3}, {%4,%5,%6,%7}, {%8,%9}, {%0,%1,%2,%3};"
                        : "+f"(acc[mt][j][0]), "+f"(acc[mt][j][1]),
                          "+f"(acc[mt][j][2]), "+f"(acc[mt][j][3])
                        : "r"(a[mt][0]), "r"(a[mt][1]), "r"(a[mt][2]), "r"(a[mt][3]),
                          "r"(b0), "r"(b1));
                }
            }
        }

        // epilogue: wei = sigmoid(xl + xg); xi = x*(1+wei) into xT in place
#pragma unroll
        for (int mt = 0; mt < 2; mt++) {
            int prow = mbase + mt * 16 + (lane >> 2);
#pragma unroll
            for (int j = 0; j < 8; j++) {
                int c0 = 8 * j + 2 * (lane & 3);
                float xg0 = s_xg[c0], xg1 = s_xg[c0 + 1];
#pragma unroll
                for (int h = 0; h < 2; h++) {
                    int p = prow + 8 * h;
                    float w0 = 1.0f + sigmoidf_fast(acc[mt][j][2 * h]     + xg0);
                    float w1 = 1.0f + sigmoidf_fast(acc[mt][j][2 * h + 1] + xg1);
                    xT[c0 * XT_S + p]       *= w0;
                    xT[(c0 + 1) * XT_S + p] *= w1;
                }
            }
        }
    }
    __syncthreads();

    // ---- phase C: per-pillar partial (max,sum) per 64-pt subtile -> 2-slot scratch ----
    {
        int h = li >> 6, c = li & 63;
        int p = h * 64, pend = p + 64; if (pend > cnt) pend = cnt;
        if (p < pend) {
            int mytile = (base >> 6) + h;
            int cur = s_u[p];
            float v = xT[c * XT_S + p];
            float mx = v, sm = v;
            for (p++; p < pend; p++) {
                int u = s_u[p];
                float w = xT[c * XT_S + p];
                if (u != cur) {
                    size_t slot = ((g_segstart[cur] >> 6) == mytile) ? 0 : 1;
                    size_t idx = slot * ((size_t)SMAX * C) + (size_t)cur * C + c;
                    g_pmax[idx] = mx;
                    g_psum[idx] = sm;
                    cur = u; mx = w; sm = w;
                } else {
                    mx = fmaxf(mx, w); sm += w;
                }
            }
            size_t slot = ((g_segstart[cur] >> 6) == mytile) ? 0 : 1;
            size_t idx = slot * ((size_t)SMAX * C) + (size_t)cur * C + c;
            g_pmax[idx] = mx;
            g_psum[idx] = sm;
        }
    }
}

// ---------------- K7: combine per-pillar partials -> out ----------------
__global__ __launch_bounds__(256) void k_combine(float* __restrict__ out, int s_count) {
    int s = blockIdx.x * 8 + (threadIdx.x >> 5);
    int lane = threadIdx.x & 31;
    if (s >= s_count) return;
    int p0 = g_segstart[s], p1 = g_segstart[s + 1];
    size_t i0 = (size_t)s * C + 2 * lane;
    if (p1 <= p0) {
        out[i0] = 0.0f; out[i0 + 1] = 0.0f;
        return;
    }
    float2 m = *reinterpret_cast<const float2*>(g_pmax + i0);
    float2 q = *reinterpret_cast<const float2*>(g_psum + i0);
    if (((p1 - 1) >> 6) > (p0 >> 6)) {
        size_t i1 = (size_t)SMAX * C + i0;
        float2 m1 = *reinterpret_cast<const float2*>(g_pmax + i1);
        float2 q1 = *reinterpret_cast<const float2*>(g_psum + i1);
        m.x = fmaxf(m.x, m1.x); m.y = fmaxf(m.y, m1.y);
        q.x += q1.x; q.y += q1.y;
    }
    *reinterpret_cast<float2*>(out + i0) = make_float2(m.x + q.x, m.y + q.y);
}

// ---------------- launch ----------------
extern "C" void kernel_launch(void* const* d_in, const int* in_sizes, int n_in,
                              void* d_out, int out_size) {
    const float* inp   = (const float*)d_in[0];
    const int*   unq   = (const int*)d_in[1];
    const float* W     = (const float*)d_in[2];
    const float* gamma = (const float*)d_in[3];
    const float* beta  = (const float*)d_in[4];
    const float* dw1   = (const float*)d_in[5];
    const float* pw1   = (const float*)d_in[6];
    const float* dw2   = (const float*)d_in[7];
    const float* pw2   = (const float*)d_in[8];
    float* out = (float*)d_out;

    int n = in_sizes[0] / CIN;     // 1,000,000
    int s = out_size / C;          // 30,000

    static bool attr_done = false;
    if (!attr_done) {
        cudaFuncSetAttribute(k_pipe, cudaFuncAttributeMaxDynamicSharedMemorySize,
                             PIPE_SMEM);
        attr_done = true;
    }

    k_bounds<<<(n + 255) / 256, 256>>>(unq, n, s);                 // launch 1
    k_moments<<<592, 256>>>(inp, n);                               // launch 2
    k_fold<<<1, 64>>>(W, gamma, beta, dw1, n);                     // launch 3
    k_gpass<<<592, 256>>>(inp, n);                                 // launch 4
    k_xg<<<1, 64>>>(dw2, pw2, n);                                  // launch 5
    k_pipe<<<(n + 127) / 128, 128, PIPE_SMEM>>>(inp, pw1, unq, n); // launch 6
    k_combine<<<(s + 7) / 8, 256>>>(out, s);                       // launch 7
}

// round 14
// speedup vs baseline: 1.4005x; 1.4005x over previous
#include <cuda_runtime.h>
#include <cstdint>

#define CIN  10
#define C    64
#define SMAX 30001
#define EPS  1e-3f
#define FULLMASK 0xffffffffu

typedef unsigned long long u64;

// ---------------- parameter staging (read by k_pipe into shared) ----------------
struct Params {
    u64   Wfp[32 * CIN];   // BN-folded linear weights, channel-pair packed
    u64   biasp[32];
    u64   dwp[32];
    float xg[C];
};
__device__ Params g_stage;

// ---------------- device scratch ----------------
__device__ float g_m1[CIN];
__device__ float g_m2[55];
__device__ float g_Wf[C * CIN];
__device__ float g_bias[C];
__device__ float g_gsum[C];
__device__ int   g_segstart[SMAX];
// per-pillar partials, 2 slots (pillar-start subtile / spill subtile)
__device__ float g_pmax[(size_t)2 * SMAX * C];
__device__ float g_psum[(size_t)2 * SMAX * C];

// ---------------- packed f32x2 / bf16 helpers ----------------
__device__ __forceinline__ u64 pack2(float lo, float hi) {
    u64 r; asm("mov.b64 %0, {%1, %2};" : "=l"(r) : "f"(lo), "f"(hi)); return r;
}
__device__ __forceinline__ void unpack2(u64 v, float& lo, float& hi) {
    asm("mov.b64 {%0, %1}, %2;" : "=f"(lo), "=f"(hi) : "l"(v));
}
__device__ __forceinline__ u64 fma2(u64 a, u64 b, u64 c) {
    u64 d; asm("fma.rn.f32x2 %0, %1, %2, %3;" : "=l"(d) : "l"(a), "l"(b), "l"(c)); return d;
}
__device__ __forceinline__ u64 mul2(u64 a, u64 b) {
    u64 d; asm("mul.rn.f32x2 %0, %1, %2;" : "=l"(d) : "l"(a), "l"(b)); return d;
}
// pack two f32 -> bf16x2 (hi goes to upper half)
__device__ __forceinline__ unsigned int cvt2bf(float hi, float lo) {
    unsigned int r;
    asm("cvt.rn.satfinite.bf16x2.f32 %0, %1, %2;" : "=r"(r) : "f"(hi), "f"(lo));
    return r;
}

__device__ __forceinline__ float sigmoidf_fast(float z) {
    return __fdividef(1.0f, 1.0f + __expf(-z));
}
__device__ __forceinline__ float warp_sum(float v) {
#pragma unroll
    for (int o = 16; o > 0; o >>= 1) v += __shfl_down_sync(FULLMASK, v, o);
    return v;
}

// ---------------- K1: zero accumulators + segment boundaries ----------------
__global__ void k_bounds(const int* __restrict__ unq, int n, int s_count) {
    if (blockIdx.x == 0) {
        int t = threadIdx.x;
        if (t < CIN) g_m1[t] = 0.0f;
        if (t < 55)  g_m2[t] = 0.0f;
        if (t < C)   g_gsum[t] = 0.0f;
    }
    int i = blockIdx.x * blockDim.x + threadIdx.x;
    if (i >= n) return;
    int cur = unq[i];
    if (i == 0) {
        for (int t = 0; t <= cur; t++) g_segstart[t] = 0;
    } else {
        int prev = unq[i - 1];
        for (int t = prev + 1; t <= cur; t++) g_segstart[t] = i;
    }
    if (i == n - 1) {
        for (int t = cur + 1; t <= s_count; t++) g_segstart[t] = n;
    }
}

// ---------------- K2: input first/second moments ----------------
__global__ void k_moments(const float* __restrict__ inp, int n) {
    float a1[CIN];
    float a2[55];
#pragma unroll
    for (int k = 0; k < CIN; k++) a1[k] = 0.0f;
#pragma unroll
    for (int k = 0; k < 55; k++) a2[k] = 0.0f;

    int stride = gridDim.x * blockDim.x;
    for (int i = blockIdx.x * blockDim.x + threadIdx.x; i < n; i += stride) {
        const float* row = inp + (size_t)i * CIN;
        float v[CIN];
#pragma unroll
        for (int k = 0; k < CIN; k++) v[k] = __ldg(row + k);
        int t = 0;
#pragma unroll
        for (int j = 0; j < CIN; j++) {
            a1[j] += v[j];
#pragma unroll
            for (int k = j; k < CIN; k++) { a2[t] += v[j] * v[k]; t++; }
        }
    }

    int lane = threadIdx.x & 31;
#pragma unroll
    for (int j = 0; j < CIN; j++) {
        float r = warp_sum(a1[j]);
        if (lane == 0) atomicAdd(&g_m1[j], r);
    }
#pragma unroll
    for (int t = 0; t < 55; t++) {
        float r = warp_sum(a2[t]);
        if (lane == 0) atomicAdd(&g_m2[t], r);
    }
}

// ---------------- K3: fold BN into linear + stage packed params ----------------
__global__ void k_fold(const float* __restrict__ W, const float* __restrict__ gamma,
                       const float* __restrict__ beta, const float* __restrict__ dw1,
                       int n) {
    int c = threadIdx.x;
    if (c < C) {
        float invn = 1.0f / (float)n;
        float wr[CIN];
#pragma unroll
        for (int k = 0; k < CIN; k++) wr[k] = W[c * CIN + k];

        float mu = 0.0f;
#pragma unroll
        for (int k = 0; k < CIN; k++) mu += wr[k] * g_m1[k];
        mu *= invn;

        float ex2 = 0.0f;
        int t = 0;
#pragma unroll
        for (int j = 0; j < CIN; j++) {
#pragma unroll
            for (int k = j; k < CIN; k++) {
                float f = wr[j] * wr[k] * g_m2[t];
                ex2 += (k == j) ? f : 2.0f * f;
                t++;
            }
        }
        ex2 *= invn;
        float var = ex2 - mu * mu;
        float alpha = gamma[c] * rsqrtf(var + EPS);
        g_bias[c] = beta[c] - mu * alpha;
#pragma unroll
        for (int k = 0; k < CIN; k++) g_Wf[c * CIN + k] = alpha * wr[k];
    }
    __syncthreads();
    if (c < 32) {
#pragma unroll
        for (int k = 0; k < CIN; k++)
            g_stage.Wfp[c * CIN + k] = pack2(g_Wf[(2 * c) * CIN + k],
                                             g_Wf[(2 * c + 1) * CIN + k]);
        g_stage.biasp[c] = pack2(g_bias[2 * c], g_bias[2 * c + 1]);
        g_stage.dwp[c]   = pack2(dw1[2 * c], dw1[2 * c + 1]);
    }
}

// ---------------- K4: g = sum over points of relu(x), channel-per-thread ----------------
#define GP_TILE 256
__global__ __launch_bounds__(256) void k_gpass(const float* __restrict__ inp, int n) {
    __shared__ __align__(16) float s_v[GP_TILE * 12];
    __shared__ float s_acc[C];

    int t = threadIdx.x;
    int c = t & 63, g = t >> 6;

    float w[CIN];
#pragma unroll
    for (int k = 0; k < CIN; k++) w[k] = g_Wf[c * CIN + k];
    float b = g_bias[c];
    if (t < C) s_acc[t] = 0.0f;

    float acc = 0.0f;
    for (int base = blockIdx.x * GP_TILE; base < n; base += gridDim.x * GP_TILE) {
        int cnt = n - base; if (cnt > GP_TILE) cnt = GP_TILE;
        __syncthreads();
        for (int i = t; i < cnt * CIN; i += 256) {
            int r = i / CIN, k = i - r * CIN;
            s_v[r * 12 + k] = inp[(size_t)base * CIN + i];
        }
        __syncthreads();
        int p0 = g * 64, p1 = p0 + 64; if (p1 > cnt) p1 = cnt;
        for (int p = p0; p < p1; p++) {
            const float* vr = s_v + p * 12;
            float4 va = *reinterpret_cast<const float4*>(vr);
            float4 vb = *reinterpret_cast<const float4*>(vr + 4);
            float2 vc = *reinterpret_cast<const float2*>(vr + 8);
            float x = b;
            x += w[0] * va.x; x += w[1] * va.y; x += w[2] * va.z; x += w[3] * va.w;
            x += w[4] * vb.x; x += w[5] * vb.y; x += w[6] * vb.z; x += w[7] * vb.w;
            x += w[8] * vc.x; x += w[9] * vc.y;
            acc += fmaxf(x, 0.0f);
        }
    }
    atomicAdd(&s_acc[c], acc);
    __syncthreads();
    if (t < C) atomicAdd(&g_gsum[t], s_acc[t]);
}

// ---------------- K5: global branch -> stage xg ----------------
__global__ void k_xg(const float* __restrict__ dw2, const float* __restrict__ pw2, int n) {
    __shared__ float t[C];
    int c = threadIdx.x;
    if (c < C) t[c] = fmaxf(dw2[c] * (g_gsum[c] / (float)n), 0.0f);
    __syncthreads();
    if (c >= C) return;
    float acc = 0.0f;
#pragma unroll
    for (int k = 0; k < C; k++) acc += pw2[c * C + k] * t[k];
    g_stage.xg[c] = acc;
}

// ---------------- K6: fused pipeline, bf16 mma.sync phase B ----------------
// dynamic shared layout (bytes):
//   xT   [64][130] f32      @ 0      (33280)  x then xi, transposed [ch][pt]
//   swA  [128 pt][144B]     @ 33280  (18432)  sw bf16, row = point, 64 k + pad
//   pwB  [64 n][144B]       @ 51712  (9216)   pw1 bf16, row = out-ch, 64 k + pad
//   Wfp  [32*10]   u64      @ 60928  (2560)
//   bp   [32]      u64      @ 63488  (256)
//   dwp  [32]      u64      @ 63744  (256)
//   xg   [64]      f32      @ 64000  (256)
//   s_u  [128]     int      @ 64256  (512)
#define XT_S    130
#define SWA_STRIDE_B 144
#define PWB_STRIDE_B 144
#define OFF_SWA 33280
#define OFF_PWB 51712
#define OFF_WFP 60928
#define OFF_BP  63488
#define OFF_DWP 63744
#define OFF_XG  64000
#define OFF_U   64256
#define PIPE_SMEM 64768

__global__ __launch_bounds__(128, 3) void k_pipe(const float* __restrict__ inp,
                                                 const float* __restrict__ pw1,
                                                 const int* __restrict__ unq,
                                                 int n) {
    extern __shared__ __align__(16) char dsm[];
    float* xT   = reinterpret_cast<float*>(dsm);
    unsigned int* swA32 = reinterpret_cast<unsigned int*>(dsm + OFF_SWA);
    unsigned int* pwB32 = reinterpret_cast<unsigned int*>(dsm + OFF_PWB);
    const ulonglong2* Wfp2 = reinterpret_cast<const ulonglong2*>(dsm + OFF_WFP);
    u64*   wfpw = reinterpret_cast<u64*>(dsm + OFF_WFP);
    u64*   bp   = reinterpret_cast<u64*>(dsm + OFF_BP);
    u64*   dwp  = reinterpret_cast<u64*>(dsm + OFF_DWP);
    float* s_xg = reinterpret_cast<float*>(dsm + OFF_XG);
    int*   s_u  = reinterpret_cast<int*>(dsm + OFF_U);

    int li = threadIdx.x;
    int base = blockIdx.x * 128;
    int cnt = n - base; if (cnt > 128) cnt = 128;

    // staging: pw1 [c][k] f32 -> pwB bf16 rows (n-major, k contiguous)
    for (int idx = li; idx < 2048; idx += 128) {
        int c = idx >> 5, kp = idx & 31;
        float2 v = __ldg(reinterpret_cast<const float2*>(pw1 + c * C + 2 * kp));
        pwB32[c * 36 + kp] = cvt2bf(v.y, v.x);
    }
    for (int t = li; t < 32 * CIN; t += 128) wfpw[t] = g_stage.Wfp[t];
    if (li < 32) { bp[li] = g_stage.biasp[li]; dwp[li] = g_stage.dwp[li]; }
    if (li < C) s_xg[li] = g_stage.xg[li];
    if (li < cnt) s_u[li] = __ldg(unq + base + li);
    __syncthreads();

    // ---- phase A: per-point folded linear + relu + swish (x -> xT, sw -> swA bf16) ----
    if (li < cnt) {
        const float* row = inp + (size_t)(base + li) * CIN;
        u64 vd[CIN];
#pragma unroll
        for (int k = 0; k < CIN; k++) {
            float f = __ldg(row + k);
            vd[k] = pack2(f, f);
        }
#pragma unroll
        for (int cp = 0; cp < 32; cp++) {
            ulonglong2 wA = Wfp2[cp * 5 + 0];
            ulonglong2 wB = Wfp2[cp * 5 + 1];
            ulonglong2 wC = Wfp2[cp * 5 + 2];
            ulonglong2 wD = Wfp2[cp * 5 + 3];
            ulonglong2 wE = Wfp2[cp * 5 + 4];
            u64 a = bp[cp];
            a = fma2(wA.x, vd[0], a); a = fma2(wA.y, vd[1], a);
            a = fma2(wB.x, vd[2], a); a = fma2(wB.y, vd[3], a);
            a = fma2(wC.x, vd[4], a); a = fma2(wC.y, vd[5], a);
            a = fma2(wD.x, vd[6], a); a = fma2(wD.y, vd[7], a);
            a = fma2(wE.x, vd[8], a); a = fma2(wE.y, vd[9], a);
            float lo, hi; unpack2(a, lo, hi);
            lo = fmaxf(lo, 0.0f); hi = fmaxf(hi, 0.0f);
            xT[(2 * cp) * XT_S + li]     = lo;
            xT[(2 * cp + 1) * XT_S + li] = hi;
            u64 sp = mul2(pack2(lo, hi), dwp[cp]);
            float sa, sb; unpack2(sp, sa, sb);
            float swa = sa * sigmoidf_fast(sa);
            float swb = sb * sigmoidf_fast(sb);
            swA32[li * 36 + cp] = cvt2bf(swb, swa);   // lo16 = k even, hi16 = k odd
        }
    } else {
#pragma unroll
        for (int c = 0; c < C; c++) xT[c * XT_S + li] = 0.0f;
#pragma unroll
        for (int cp = 0; cp < 32; cp++) swA32[li * 36 + cp] = 0u;
    }
    __syncthreads();

    // ---- phase B: tensor-core GEMM xl[p][c] = sum_k sw[p][k] * pwB[c][k] ----
    {
        int w = li >> 5, lane = li & 31;
        int mbase = w * 32;

        unsigned swA_base = (unsigned)__cvta_generic_to_shared(dsm + OFF_SWA);
        unsigned pwB_base = (unsigned)__cvta_generic_to_shared(dsm + OFF_PWB);

        float acc[2][8][4];
#pragma unroll
        for (int mt = 0; mt < 2; mt++)
#pragma unroll
            for (int j = 0; j < 8; j++)
#pragma unroll
                for (int r = 0; r < 4; r++) acc[mt][j][r] = 0.0f;

#pragma unroll
        for (int t = 0; t < 4; t++) {
            unsigned int a[2][4];
#pragma unroll
            for (int mt = 0; mt < 2; mt++) {
                unsigned addrA = swA_base
                    + (mbase + mt * 16 + (lane & 15)) * SWA_STRIDE_B
                    + (lane >> 4) * 16 + t * 32;
                asm volatile(
                    "ldmatrix.sync.aligned.m8n8.x4.shared.b16 {%0,%1,%2,%3}, [%4];"
                    : "=r"(a[mt][0]), "=r"(a[mt][1]), "=r"(a[mt][2]), "=r"(a[mt][3])
                    : "r"(addrA));
            }
#pragma unroll
            for (int j = 0; j < 8; j++) {
                unsigned int b0, b1;
                unsigned addrB = pwB_base
                    + (8 * j + (lane & 7)) * PWB_STRIDE_B
                    + ((lane >> 3) & 1) * 16 + t * 32;
                asm volatile(
                    "ldmatrix.sync.aligned.m8n8.x2.shared.b16 {%0,%1}, [%2];"
                    : "=r"(b0), "=r"(b1) : "r"(addrB));
#pragma unroll
                for (int mt = 0; mt < 2; mt++) {
                    asm volatile(
                        "mma.sync.aligned.m16n8k16.row.col.f32.bf16.bf16.f32 "
                        "{%0,%1,%2,%3}, {%4,%5,%6,%7}, {%8,%9}, {%0,%1,%2,%3};"
                        : "+f"(acc[mt][j][0]), "+f"(acc[mt][j][1]),
                          "+f"(acc[mt][j][2]), "+f"(acc[mt][j][3])
                        : "r"(a[mt][0]), "r"(a[mt][1]), "r"(a[mt][2]), "r"(a[mt][3]),
                          "r"(b0), "r"(b1));
                }
            }
        }

        // epilogue: wei = sigmoid(xl + xg); xi = x*(1+wei) into xT in place
#pragma unroll
        for (int mt = 0; mt < 2; mt++) {
            int prow = mbase + mt * 16 + (lane >> 2);
#pragma unroll
            for (int j = 0; j < 8; j++) {
                int c0 = 8 * j + 2 * (lane & 3);
                float xg0 = s_xg[c0], xg1 = s_xg[c0 + 1];
#pragma unroll
                for (int h = 0; h < 2; h++) {
                    int p = prow + 8 * h;
                    float w0 = 1.0f + sigmoidf_fast(acc[mt][j][2 * h]     + xg0);
                    float w1 = 1.0f + sigmoidf_fast(acc[mt][j][2 * h + 1] + xg1);
                    xT[c0 * XT_S + p]       *= w0;
                    xT[(c0 + 1) * XT_S + p] *= w1;
                }
            }
        }
    }
    __syncthreads();

    // ---- phase C: per-pillar partial (max,sum) per 64-pt subtile -> 2-slot scratch ----
    {
        int h = li >> 6, c = li & 63;
        int p = h * 64, pend = p + 64; if (pend > cnt) pend = cnt;
        if (p < pend) {
            int mytile = (base >> 6) + h;
            int cur = s_u[p];
            float v = xT[c * XT_S + p];
            float mx = v, sm = v;
            for (p++; p < pend; p++) {
                int u = s_u[p];
                float w = xT[c * XT_S + p];
                if (u != cur) {
                    size_t slot = ((g_segstart[cur] >> 6) == mytile) ? 0 : 1;
                    size_t idx = slot * ((size_t)SMAX * C) + (size_t)cur * C + c;
                    g_pmax[idx] = mx;
                    g_psum[idx] = sm;
                    cur = u; mx = w; sm = w;
                } else {
                    mx = fmaxf(mx, w); sm += w;
                }
            }
            size_t slot = ((g_segstart[cur] >> 6) == mytile) ? 0 : 1;
            size_t idx = slot * ((size_t)SMAX * C) + (size_t)cur * C + c;
            g_pmax[idx] = mx;
            g_psum[idx] = sm;
        }
    }
}

// ---------------- K7: combine per-pillar partials -> out ----------------
__global__ __launch_bounds__(256) void k_combine(float* __restrict__ out, int s_count) {
    int s = blockIdx.x * 8 + (threadIdx.x >> 5);
    int lane = threadIdx.x & 31;
    if (s >= s_count) return;
    int p0 = g_segstart[s], p1 = g_segstart[s + 1];
    size_t i0 = (size_t)s * C + 2 * lane;
    if (p1 <= p0) {
        out[i0] = 0.0f; out[i0 + 1] = 0.0f;
        return;
    }
    float2 m = *reinterpret_cast<const float2*>(g_pmax + i0);
    float2 q = *reinterpret_cast<const float2*>(g_psum + i0);
    if (((p1 - 1) >> 6) > (p0 >> 6)) {
        size_t i1 = (size_t)SMAX * C + i0;
        float2 m1 = *reinterpret_cast<const float2*>(g_pmax + i1);
        float2 q1 = *reinterpret_cast<const float2*>(g_psum + i1);
        m.x = fmaxf(m.x, m1.x); m.y = fmaxf(m.y, m1.y);
        q.x += q1.x; q.y += q1.y;
    }
    *reinterpret_cast<float2*>(out + i0) = make_float2(m.x + q.x, m.y + q.y);
}

// ---------------- launch ----------------
extern "C" void kernel_launch(void* const* d_in, const int* in_sizes, int n_in,
                              void* d_out, int out_size) {
    const float* inp   = (const float*)d_in[0];
    const int*   unq   = (const int*)d_in[1];
    const float* W     = (const float*)d_in[2];
    const float* gamma = (const float*)d_in[3];
    const float* beta  = (const float*)d_in[4];
    const float* dw1   = (const float*)d_in[5];
    const float* pw1   = (const float*)d_in[6];
    const float* dw2   = (const float*)d_in[7];
    const float* pw2   = (const float*)d_in[8];
    float* out = (float*)d_out;

    int n = in_sizes[0] / CIN;     // 1,000,000
    int s = out_size / C;          // 30,000

    static bool attr_done = false;
    if (!attr_done) {
        cudaFuncSetAttribute(k_pipe, cudaFuncAttributeMaxDynamicSharedMemorySize,
                             PIPE_SMEM);
        attr_done = true;
    }

    k_bounds<<<(n + 255) / 256, 256>>>(unq, n, s);                 // launch 1
    k_moments<<<592, 256>>>(inp, n);                               // launch 2
    k_fold<<<1, 64>>>(W, gamma, beta, dw1, n);                     // launch 3
    k_gpass<<<592, 256>>>(inp, n);                                 // launch 4
    k_xg<<<1, 64>>>(dw2, pw2, n);                                  // launch 5
    k_pipe<<<(n + 127) / 128, 128, PIPE_SMEM>>>(inp, pw1, unq, n); // launch 6
    k_combine<<<(s + 7) / 8, 256>>>(out, s);                       // launch 7
}